// round 4
// baseline (speedup 1.0000x reference)
#include <cuda_runtime.h>

#define NN 50000
#define EE 800000
#define CH 256

// ---- scratch (device globals; no allocation allowed) ----
__device__ float g_xw[(size_t)NN * CH];   // x @ W            (51.2 MB)
__device__ int   g_deg[NN];
__device__ int   g_off[NN + 1];
__device__ int   g_cur[NN];
__device__ int   g_esrc[EE];
__device__ float g_eval[EE];

// ---------------------------------------------------------------- CSR build
__global__ void zero_deg_kernel() {
    int i = blockIdx.x * blockDim.x + threadIdx.x;
    if (i < NN) g_deg[i] = 0;
}

__global__ void hist_kernel(const int* __restrict__ dst, int E) {
    int i = blockIdx.x * blockDim.x + threadIdx.x;
    if (i < E) atomicAdd(&g_deg[dst[i]], 1);
}

// single-block exclusive scan over g_deg -> g_off / g_cur
__global__ void scan_kernel(int E) {
    __shared__ int wsum[32];
    __shared__ int carry;
    if (threadIdx.x == 0) carry = 0;
    __syncthreads();
    int lane = threadIdx.x & 31, warp = threadIdx.x >> 5;
    for (int base = 0; base < NN; base += 1024) {
        int i = base + (int)threadIdx.x;
        int v = (i < NN) ? g_deg[i] : 0;
        int x = v;
        #pragma unroll
        for (int o = 1; o < 32; o <<= 1) {
            int y = __shfl_up_sync(0xffffffffu, x, o);
            if (lane >= o) x += y;
        }
        if (lane == 31) wsum[warp] = x;
        __syncthreads();
        if (warp == 0) {
            int t = wsum[lane];
            #pragma unroll
            for (int o = 1; o < 32; o <<= 1) {
                int y = __shfl_up_sync(0xffffffffu, t, o);
                if (lane >= o) t += y;
            }
            wsum[lane] = t;
        }
        __syncthreads();
        int incl = x + (warp > 0 ? wsum[warp - 1] : 0);
        int excl = carry + incl - v;
        if (i < NN) { g_off[i] = excl; g_cur[i] = excl; }
        __syncthreads();                       // all reads of carry/wsum done
        if (threadIdx.x == 1023) carry += incl;  // incl of last thread = chunk total
        __syncthreads();
    }
    if (threadIdx.x == 0) g_off[NN] = E;
}

__global__ void scatter_kernel(const int* __restrict__ src,
                               const int* __restrict__ dst,
                               const float* __restrict__ val, int E) {
    int i = blockIdx.x * blockDim.x + threadIdx.x;
    if (i < E) {
        int p = atomicAdd(&g_cur[dst[i]], 1);
        g_esrc[p] = src[i];
        g_eval[p] = val[i];
    }
}

// ---------------------------------------------------------------- GEMM
// C[M,256] = A[M,256] @ B[256,256], fp32, 128x128x8 tiles, 8x8 per thread.
#define BM 128
#define BN 128
#define BK 8
#define TM 8
#define TN 8

__global__ __launch_bounds__(256, 2)
void gemm_kernel(const float* __restrict__ A, const float* __restrict__ B, int M) {
    __shared__ float As[BK][BM];
    __shared__ float Bs[BK][BN];
    const int K = CH, N = CH;
    int bm = blockIdx.y * BM;
    int bn = blockIdx.x * BN;
    int tid = threadIdx.x;

    int a_row  = tid >> 1;          // 0..127
    int a_col4 = (tid & 1) * 4;     // 0 or 4
    int b_row  = tid >> 5;          // 0..7
    int b_col4 = (tid & 31) * 4;    // 0..124
    int tr = (tid >> 4) * TM;       // 0..120
    int tc = (tid & 15) * TN;       // 0..120

    float acc[TM][TN];
    #pragma unroll
    for (int i = 0; i < TM; i++)
        #pragma unroll
        for (int j = 0; j < TN; j++) acc[i][j] = 0.f;

    for (int k0 = 0; k0 < K; k0 += BK) {
        float4 av = make_float4(0.f, 0.f, 0.f, 0.f);
        int gr = bm + a_row;
        if (gr < M) av = *(const float4*)&A[(size_t)gr * K + k0 + a_col4];
        As[a_col4 + 0][a_row] = av.x;
        As[a_col4 + 1][a_row] = av.y;
        As[a_col4 + 2][a_row] = av.z;
        As[a_col4 + 3][a_row] = av.w;
        *(float4*)&Bs[b_row][b_col4] =
            *(const float4*)&B[(size_t)(k0 + b_row) * N + bn + b_col4];
        __syncthreads();
        #pragma unroll
        for (int k = 0; k < BK; ++k) {
            float4 a0 = *(float4*)&As[k][tr];
            float4 a1 = *(float4*)&As[k][tr + 4];
            float4 b0 = *(float4*)&Bs[k][tc];
            float4 b1 = *(float4*)&Bs[k][tc + 4];
            float ar[TM] = {a0.x, a0.y, a0.z, a0.w, a1.x, a1.y, a1.z, a1.w};
            float br[TN] = {b0.x, b0.y, b0.z, b0.w, b1.x, b1.y, b1.z, b1.w};
            #pragma unroll
            for (int i = 0; i < TM; i++)
                #pragma unroll
                for (int j = 0; j < TN; j++)
                    acc[i][j] += ar[i] * br[j];
        }
        __syncthreads();
    }

    #pragma unroll
    for (int i = 0; i < TM; i++) {
        int gr = bm + tr + i;
        if (gr >= M) break;
        #pragma unroll
        for (int j = 0; j < TN; j += 4) {
            *(float4*)&g_xw[(size_t)gr * N + bn + tc + j] =
                make_float4(acc[i][j], acc[i][j + 1], acc[i][j + 2], acc[i][j + 3]);
        }
    }
}

// ---------------------------------------------------------------- gather
// out[d][c] = b[c] + sum over incoming edges of val * xw[src][c]
__global__ void gather_kernel(const float* __restrict__ bias,
                              float* __restrict__ out) {
    int d = blockIdx.x;
    int c = threadIdx.x;
    int s = g_off[d], e = g_off[d + 1];
    float acc = bias[c];
    int j = s;
    for (; j + 4 <= e; j += 4) {
        int   s0 = g_esrc[j],     s1 = g_esrc[j + 1];
        int   s2 = g_esrc[j + 2], s3 = g_esrc[j + 3];
        float v0 = g_eval[j],     v1 = g_eval[j + 1];
        float v2 = g_eval[j + 2], v3 = g_eval[j + 3];
        float x0 = g_xw[(size_t)s0 * CH + c];
        float x1 = g_xw[(size_t)s1 * CH + c];
        float x2 = g_xw[(size_t)s2 * CH + c];
        float x3 = g_xw[(size_t)s3 * CH + c];
        acc += v0 * x0;
        acc += v1 * x1;
        acc += v2 * x2;
        acc += v3 * x3;
    }
    for (; j < e; ++j)
        acc += g_eval[j] * g_xw[(size_t)g_esrc[j] * CH + c];
    out[(size_t)d * CH + c] = acc;
}

// ---------------------------------------------------------------- launch
extern "C" void kernel_launch(void* const* d_in, const int* in_sizes, int n_in,
                              void* d_out, int out_size) {
    const float* x    = (const float*)d_in[0];   // [N, 256]
    const float* W    = (const float*)d_in[1];   // [256, 256]
    const float* bias = (const float*)d_in[2];   // [256]
    const int*   esrc = (const int*)d_in[3];     // [E]
    const int*   edst = (const int*)d_in[4];     // [E]
    const float* eval = (const float*)d_in[5];   // [E]
    float* out = (float*)d_out;

    int M = in_sizes[0] / CH;   // 50000
    int E = in_sizes[3];        // 800000

    // CSR-by-dst build (avoids 204.8M float atomics in the aggregation)
    zero_deg_kernel<<<(NN + 255) / 256, 256>>>();
    hist_kernel<<<(E + 255) / 256, 256>>>(edst, E);
    scan_kernel<<<1, 1024>>>(E);
    scatter_kernel<<<(E + 255) / 256, 256>>>(esrc, edst, eval, E);

    // xw = x @ W
    dim3 ggrid(CH / BN, (M + BM - 1) / BM);
    gemm_kernel<<<ggrid, 256>>>(x, W, M);

    // out = segment_sum + bias (atomic-free)
    gather_kernel<<<M, CH>>>(bias, out);
}

// round 6
// speedup vs baseline: 1.8737x; 1.8737x over previous
#include <cuda_runtime.h>
#include <cuda_bf16.h>
#include <cstdint>

#define NN 50000
#define EE 800000
#define CH 256
#define PAD_M 50048          // 391 * 128

// ---- scratch (device globals; no allocation allowed) ----
__device__ __align__(16) float g_xw[(size_t)NN * CH];              // x @ W (51.2 MB)
__device__ int   g_deg[NN];
__device__ int   g_off[NN + 1];
__device__ int   g_cur[NN];
__device__ int   g_esrc[EE];
__device__ float g_eval[EE];
__device__ __align__(16) __nv_bfloat16 g_xhi[(size_t)PAD_M * CH];  // 25.6 MB
__device__ __align__(16) __nv_bfloat16 g_xlo[(size_t)PAD_M * CH];  // 25.6 MB
__device__ __align__(16) __nv_bfloat16 g_wthi[CH * CH];            // W^T hi [n][k]
__device__ __align__(16) __nv_bfloat16 g_wtlo[CH * CH];            // W^T lo [n][k]

// =============================================================== helpers
__device__ __forceinline__ uint32_t smem_u32(const void* p) {
    uint32_t a;
    asm("{ .reg .u64 t; cvta.to.shared.u64 t, %1; cvt.u32.u64 %0, t; }"
        : "=r"(a) : "l"(p));
    return a;
}

__device__ __forceinline__ void cp_async16(uint32_t s, const void* g) {
    asm volatile("cp.async.cg.shared.global [%0], [%1], 16;" :: "r"(s), "l"(g));
}
__device__ __forceinline__ void cp_commit() {
    asm volatile("cp.async.commit_group;" ::: "memory");
}
template <int N>
__device__ __forceinline__ void cp_wait() {
    asm volatile("cp.async.wait_group %0;" :: "n"(N) : "memory");
}

__device__ __forceinline__ void ldsm_x4(uint32_t* r, uint32_t addr) {
    asm volatile("ldmatrix.sync.aligned.m8n8.x4.shared.b16 {%0,%1,%2,%3}, [%4];"
                 : "=r"(r[0]), "=r"(r[1]), "=r"(r[2]), "=r"(r[3]) : "r"(addr));
}

// D(fp32) += A(bf16) * B(bf16), m16n8k16, A row-major frag, B col-major frag
__device__ __forceinline__ void mma_bf16(float* c, const uint32_t* a, const uint32_t* b) {
    asm volatile(
        "mma.sync.aligned.m16n8k16.row.col.f32.bf16.bf16.f32 "
        "{%0,%1,%2,%3}, {%4,%5,%6,%7}, {%8,%9}, {%0,%1,%2,%3};"
        : "+f"(c[0]), "+f"(c[1]), "+f"(c[2]), "+f"(c[3])
        : "r"(a[0]), "r"(a[1]), "r"(a[2]), "r"(a[3]), "r"(b[0]), "r"(b[1]));
}

// =============================================================== CSR build
__global__ void zero_deg_kernel() {
    int i = blockIdx.x * blockDim.x + threadIdx.x;
    if (i < NN) g_deg[i] = 0;
}

__global__ void hist_kernel(const int* __restrict__ dst, int E) {
    int i = blockIdx.x * blockDim.x + threadIdx.x;
    if (i < E) atomicAdd(&g_deg[dst[i]], 1);
}

__global__ void scan_kernel(int E) {
    __shared__ int wsum[32];
    __shared__ int carry;
    if (threadIdx.x == 0) carry = 0;
    __syncthreads();
    int lane = threadIdx.x & 31, warp = threadIdx.x >> 5;
    for (int base = 0; base < NN; base += 1024) {
        int i = base + (int)threadIdx.x;
        int v = (i < NN) ? g_deg[i] : 0;
        int x = v;
        #pragma unroll
        for (int o = 1; o < 32; o <<= 1) {
            int y = __shfl_up_sync(0xffffffffu, x, o);
            if (lane >= o) x += y;
        }
        if (lane == 31) wsum[warp] = x;
        __syncthreads();
        if (warp == 0) {
            int t = wsum[lane];
            #pragma unroll
            for (int o = 1; o < 32; o <<= 1) {
                int y = __shfl_up_sync(0xffffffffu, t, o);
                if (lane >= o) t += y;
            }
            wsum[lane] = t;
        }
        __syncthreads();
        int incl = x + (warp > 0 ? wsum[warp - 1] : 0);
        int excl = carry + incl - v;
        if (i < NN) { g_off[i] = excl; g_cur[i] = excl; }
        __syncthreads();
        if (threadIdx.x == 1023) carry += incl;
        __syncthreads();
    }
    if (threadIdx.x == 0) g_off[NN] = E;
}

__global__ void scatter_kernel(const int* __restrict__ src,
                               const int* __restrict__ dst,
                               const float* __restrict__ val, int E) {
    int i = blockIdx.x * blockDim.x + threadIdx.x;
    if (i < E) {
        int p = atomicAdd(&g_cur[dst[i]], 1);
        g_esrc[p] = src[i];
        g_eval[p] = val[i];
    }
}

// =============================================================== split prep
__global__ void split_x_kernel(const float* __restrict__ x, int n4) {
    int i = blockIdx.x * blockDim.x + threadIdx.x;
    if (i >= n4) return;
    float4 v = ((const float4*)x)[i];
    union { __nv_bfloat16 b[4]; uint2 u; } H, L;
    H.b[0] = __float2bfloat16(v.x); L.b[0] = __float2bfloat16(v.x - __bfloat162float(H.b[0]));
    H.b[1] = __float2bfloat16(v.y); L.b[1] = __float2bfloat16(v.y - __bfloat162float(H.b[1]));
    H.b[2] = __float2bfloat16(v.z); L.b[2] = __float2bfloat16(v.z - __bfloat162float(H.b[2]));
    H.b[3] = __float2bfloat16(v.w); L.b[3] = __float2bfloat16(v.w - __bfloat162float(H.b[3]));
    ((uint2*)g_xhi)[i] = H.u;
    ((uint2*)g_xlo)[i] = L.u;
}

// zero the padded tail rows so their garbage never makes NaNs (cheap insurance)
__global__ void zero_pad_kernel(int M) {
    int i = blockIdx.x * blockDim.x + threadIdx.x;
    size_t base = (size_t)M * CH;
    size_t total = (size_t)PAD_M * CH;
    size_t idx = base + i;
    if (idx < total) {
        g_xhi[idx] = __float2bfloat16(0.f);
        g_xlo[idx] = __float2bfloat16(0.f);
    }
}

__global__ void split_wt_kernel(const float* __restrict__ W) {
    int k = threadIdx.x;
    int n = blockIdx.x;
    float w = W[k * CH + n];
    __nv_bfloat16 h = __float2bfloat16(w);
    g_wthi[n * CH + k] = h;
    g_wtlo[n * CH + k] = __float2bfloat16(w - __bfloat162float(h));
}

// =============================================================== mma.sync GEMM
// g_xw[M,256] = x @ W via split-bf16 (D += AhiBhi + AhiBlo + AloBhi, fp32 accum)
// CTA tile 128(m) x 128(n), BK=32, cp.async double buffer, 8 warps (4m x 2n),
// warp tile 32x64 = 2 m16-tiles x 8 n8-tiles.
// SMEM per buffer: AHI 8K | ALO 8K | BHI 8K | BLO 8K = 32K; x2 buffers = 64K.
// Row layout: 32 bf16 = 64B per row, 4 x 16B chunks, swizzle chunk ^= (row & 3).
#define SWZ(r, c) ((uint32_t)((r) * 64 + (((c) ^ ((r) & 3)) * 16)))
#define GEMM_SMEM 65536

__global__ __launch_bounds__(256, 2) void gemm_mma(int M) {
    extern __shared__ char smem[];
    const uint32_t sb = smem_u32(smem);
    const int tid  = threadIdx.x;
    const int lane = tid & 31;
    const int wid  = tid >> 5;
    const int warp_m = (wid & 3) * 32;   // 0,32,64,96
    const int warp_n = (wid >> 2) * 64;  // 0,64
    const size_t arow = (size_t)blockIdx.y * 128;
    const int bn = blockIdx.x * 128;

    float acc[2][8][4];
    #pragma unroll
    for (int mt = 0; mt < 2; mt++)
        #pragma unroll
        for (int nt = 0; nt < 8; nt++)
            #pragma unroll
            for (int j = 0; j < 4; j++) acc[mt][nt][j] = 0.f;

    // ---- fill one buffer with K-chunk `ch` (all 4 matrices) ----
    auto fill = [&](int buf, int ch) {
        const int k0 = ch * 32;
        const uint32_t base = sb + buf * 32768;
        #pragma unroll
        for (int i = 0; i < 2; i++) {
            int chunk = tid + i * 256;         // 0..511
            int r = chunk >> 2, c = chunk & 3; // row 0..127, 16B-chunk 0..3
            uint32_t so = SWZ(r, c);
            size_t ga = (arow + r) * CH + k0 + c * 8;
            size_t gb = (size_t)(bn + r) * CH + k0 + c * 8;
            cp_async16(base +     0 + so, &g_xhi[ga]);
            cp_async16(base +  8192 + so, &g_xlo[ga]);
            cp_async16(base + 16384 + so, &g_wthi[gb]);
            cp_async16(base + 24576 + so, &g_wtlo[gb]);
        }
    };

    // ---- compute on one buffer ----
    auto compute = [&](int buf) {
        const uint32_t base = sb + buf * 32768;
        #pragma unroll
        for (int ks = 0; ks < 2; ks++) {
            uint32_t a_hi[2][4], a_lo[2][4];
            const int achunk = 2 * ks + (lane >> 4);
            #pragma unroll
            for (int mt = 0; mt < 2; mt++) {
                int r = warp_m + mt * 16 + (lane & 15);
                uint32_t ad = base + SWZ(r, achunk);
                ldsm_x4(a_hi[mt], ad);
                ldsm_x4(a_lo[mt], ad + 8192);
            }
            #pragma unroll
            for (int np = 0; np < 4; np++) {
                int nr = warp_n + np * 16 + (lane & 7) + ((lane & 16) ? 8 : 0);
                int bchunk = 2 * ks + ((lane >> 3) & 1);
                uint32_t bd = base + 16384 + SWZ(nr, bchunk);
                uint32_t bhi[4], blo[4];
                ldsm_x4(bhi, bd);
                ldsm_x4(blo, bd + 8192);
                #pragma unroll
                for (int h = 0; h < 2; h++) {
                    int nt = np * 2 + h;
                    #pragma unroll
                    for (int mt = 0; mt < 2; mt++) {
                        mma_bf16(acc[mt][nt], a_hi[mt], &bhi[2 * h]);
                        mma_bf16(acc[mt][nt], a_hi[mt], &blo[2 * h]);
                        mma_bf16(acc[mt][nt], a_lo[mt], &bhi[2 * h]);
                    }
                }
            }
        }
    };

    fill(0, 0);
    cp_commit();
    #pragma unroll 1
    for (int ch = 0; ch < 8; ch++) {
        if (ch < 7) {
            fill((ch + 1) & 1, ch + 1);
            cp_commit();
            cp_wait<1>();
        } else {
            cp_wait<0>();
        }
        __syncthreads();
        compute(ch & 1);
        __syncthreads();
    }

    // ---- epilogue: c0,c1 -> (row, col..col+1); c2,c3 -> (row+8, ...) ----
    #pragma unroll
    for (int mt = 0; mt < 2; mt++) {
        size_t r0 = arow + warp_m + mt * 16 + (lane >> 2);
        #pragma unroll
        for (int nt = 0; nt < 8; nt++) {
            int gc = bn + warp_n + nt * 8 + 2 * (lane & 3);
            if (r0 < (size_t)M)
                *(float2*)&g_xw[r0 * CH + gc] =
                    make_float2(acc[mt][nt][0], acc[mt][nt][1]);
            if (r0 + 8 < (size_t)M)
                *(float2*)&g_xw[(r0 + 8) * CH + gc] =
                    make_float2(acc[mt][nt][2], acc[mt][nt][3]);
        }
    }
}

// =============================================================== gather
// out[d][c] = b[c] + sum_{edges to d} val * xw[src][c]   (atomic-free, fp32)
// 4 nodes per 256-thread block; 64 threads x float4 per node row.
__global__ __launch_bounds__(256) void gather_kernel(const float* __restrict__ bias,
                                                     float* __restrict__ out) {
    int node = blockIdx.x * 4 + (threadIdx.x >> 6);
    if (node >= NN) return;
    int c = (threadIdx.x & 63) << 2;
    int s = g_off[node], e = g_off[node + 1];
    float4 acc = *(const float4*)&bias[c];
    int j = s;
    for (; j + 4 <= e; j += 4) {
        int   s0 = g_esrc[j],     s1 = g_esrc[j + 1];
        int   s2 = g_esrc[j + 2], s3 = g_esrc[j + 3];
        float v0 = g_eval[j],     v1 = g_eval[j + 1];
        float v2 = g_eval[j + 2], v3 = g_eval[j + 3];
        float4 x0 = *(const float4*)&g_xw[(size_t)s0 * CH + c];
        float4 x1 = *(const float4*)&g_xw[(size_t)s1 * CH + c];
        float4 x2 = *(const float4*)&g_xw[(size_t)s2 * CH + c];
        float4 x3 = *(const float4*)&g_xw[(size_t)s3 * CH + c];
        acc.x += v0 * x0.x; acc.y += v0 * x0.y; acc.z += v0 * x0.z; acc.w += v0 * x0.w;
        acc.x += v1 * x1.x; acc.y += v1 * x1.y; acc.z += v1 * x1.z; acc.w += v1 * x1.w;
        acc.x += v2 * x2.x; acc.y += v2 * x2.y; acc.z += v2 * x2.z; acc.w += v2 * x2.w;
        acc.x += v3 * x3.x; acc.y += v3 * x3.y; acc.z += v3 * x3.z; acc.w += v3 * x3.w;
    }
    for (; j < e; ++j) {
        float v = g_eval[j];
        float4 x0 = *(const float4*)&g_xw[(size_t)g_esrc[j] * CH + c];
        acc.x += v * x0.x; acc.y += v * x0.y; acc.z += v * x0.z; acc.w += v * x0.w;
    }
    *(float4*)&out[(size_t)node * CH + c] = acc;
}

// =============================================================== launch
extern "C" void kernel_launch(void* const* d_in, const int* in_sizes, int n_in,
                              void* d_out, int out_size) {
    const float* x    = (const float*)d_in[0];   // [N, 256]
    const float* W    = (const float*)d_in[1];   // [256, 256]
    const float* bias = (const float*)d_in[2];   // [256]
    const int*   esrc = (const int*)d_in[3];     // [E]
    const int*   edst = (const int*)d_in[4];     // [E]
    const float* eval = (const float*)d_in[5];   // [E]
    float* out = (float*)d_out;

    int M = in_sizes[0] / CH;   // 50000
    int E = in_sizes[3];        // 800000

    cudaFuncSetAttribute(gemm_mma, cudaFuncAttributeMaxDynamicSharedMemorySize,
                         GEMM_SMEM);

    // split prep for tensor-core GEMM
    int n4 = (M * CH) / 4;
    split_x_kernel<<<(n4 + 255) / 256, 256>>>(x, n4);
    int padn = (PAD_M - M) * CH;
    if (padn > 0) zero_pad_kernel<<<(padn + 255) / 256, 256>>>(M);
    split_wt_kernel<<<CH, CH>>>(W);

    // CSR-by-dst build
    zero_deg_kernel<<<(NN + 255) / 256, 256>>>();
    hist_kernel<<<(E + 255) / 256, 256>>>(edst, E);
    scan_kernel<<<1, 1024>>>(E);
    scatter_kernel<<<(E + 255) / 256, 256>>>(esrc, edst, eval, E);

    // xw = x @ W  (mma.sync bf16-split, fp32 accum)
    dim3 ggrid(2, (M + 127) / 128);   // (n halves, m tiles)
    gemm_mma<<<ggrid, 256, GEMM_SMEM>>>(M);

    // out = segment_sum + bias
    gather_kernel<<<(NN + 3) / 4, 256>>>(bias, out);
}

// round 7
// speedup vs baseline: 2.3608x; 1.2600x over previous
#include <cuda_runtime.h>
#include <cuda_bf16.h>
#include <cstdint>

#define NN 50000
#define EE 800000
#define CH 256
#define PAD_M 50048          // 391 * 128

// ---- scratch (device globals; no allocation allowed) ----
__device__ __align__(16) float g_xw[(size_t)NN * CH];              // x @ W (51.2 MB)
__device__ int   g_deg[NN];
__device__ int   g_off[NN + 1];
__device__ int   g_cur[NN];
__device__ int   g_esrc[EE];
__device__ float g_eval[EE];
__device__ __align__(16) __nv_bfloat16 g_xhi[(size_t)PAD_M * CH];  // 25.6 MB
__device__ __align__(16) __nv_bfloat16 g_xlo[(size_t)PAD_M * CH];  // 25.6 MB
__device__ __align__(16) __nv_bfloat16 g_wthi[CH * CH];            // W^T hi [n][k]
__device__ __align__(16) __nv_bfloat16 g_wtlo[CH * CH];            // W^T lo [n][k]

// =============================================================== helpers
__device__ __forceinline__ uint32_t smem_u32(const void* p) {
    uint32_t a;
    asm("{ .reg .u64 t; cvta.to.shared.u64 t, %1; cvt.u32.u64 %0, t; }"
        : "=r"(a) : "l"(p));
    return a;
}

__device__ __forceinline__ void cp_async16(uint32_t s, const void* g) {
    asm volatile("cp.async.cg.shared.global [%0], [%1], 16;" :: "r"(s), "l"(g));
}
__device__ __forceinline__ void cp_commit() {
    asm volatile("cp.async.commit_group;" ::: "memory");
}
template <int N>
__device__ __forceinline__ void cp_wait() {
    asm volatile("cp.async.wait_group %0;" :: "n"(N) : "memory");
}

__device__ __forceinline__ void ldsm_x4(uint32_t* r, uint32_t addr) {
    asm volatile("ldmatrix.sync.aligned.m8n8.x4.shared.b16 {%0,%1,%2,%3}, [%4];"
                 : "=r"(r[0]), "=r"(r[1]), "=r"(r[2]), "=r"(r[3]) : "r"(addr));
}

// D(fp32) += A(bf16) * B(bf16), m16n8k16, A row-major frag, B col-major frag
__device__ __forceinline__ void mma_bf16(float* c, const uint32_t* a, const uint32_t* b) {
    asm volatile(
        "mma.sync.aligned.m16n8k16.row.col.f32.bf16.bf16.f32 "
        "{%0,%1,%2,%3}, {%4,%5,%6,%7}, {%8,%9}, {%0,%1,%2,%3};"
        : "+f"(c[0]), "+f"(c[1]), "+f"(c[2]), "+f"(c[3])
        : "r"(a[0]), "r"(a[1]), "r"(a[2]), "r"(a[3]), "r"(b[0]), "r"(b[1]));
}

// =============================================================== CSR build
__global__ void hist_kernel(const int* __restrict__ dst, int E) {
    int i = blockIdx.x * blockDim.x + threadIdx.x;
    if (i < E) atomicAdd(&g_deg[dst[i]], 1);
}

__global__ void scan_kernel(int E) {
    __shared__ int wsum[32];
    __shared__ int carry;
    if (threadIdx.x == 0) carry = 0;
    __syncthreads();
    int lane = threadIdx.x & 31, warp = threadIdx.x >> 5;
    for (int base = 0; base < NN; base += 1024) {
        int i = base + (int)threadIdx.x;
        int v = (i < NN) ? g_deg[i] : 0;
        int x = v;
        #pragma unroll
        for (int o = 1; o < 32; o <<= 1) {
            int y = __shfl_up_sync(0xffffffffu, x, o);
            if (lane >= o) x += y;
        }
        if (lane == 31) wsum[warp] = x;
        __syncthreads();
        if (warp == 0) {
            int t = wsum[lane];
            #pragma unroll
            for (int o = 1; o < 32; o <<= 1) {
                int y = __shfl_up_sync(0xffffffffu, t, o);
                if (lane >= o) t += y;
            }
            wsum[lane] = t;
        }
        __syncthreads();
        int incl = x + (warp > 0 ? wsum[warp - 1] : 0);
        int excl = carry + incl - v;
        if (i < NN) { g_off[i] = excl; g_cur[i] = excl; }
        __syncthreads();
        if (threadIdx.x == 1023) carry += incl;
        __syncthreads();
    }
    if (threadIdx.x == 0) g_off[NN] = E;
}

__global__ void scatter_kernel(const int* __restrict__ src,
                               const int* __restrict__ dst,
                               const float* __restrict__ val, int E) {
    int i = blockIdx.x * blockDim.x + threadIdx.x;
    if (i < E) {
        int p = atomicAdd(&g_cur[dst[i]], 1);
        g_esrc[p] = src[i];
        g_eval[p] = val[i];
    }
}

// =============================================================== split prep
__global__ void split_x_kernel(const float* __restrict__ x, int n4) {
    int i = blockIdx.x * blockDim.x + threadIdx.x;
    if (i >= n4) return;
    float4 v = ((const float4*)x)[i];
    union { __nv_bfloat16 b[4]; uint2 u; } H, L;
    H.b[0] = __float2bfloat16(v.x); L.b[0] = __float2bfloat16(v.x - __bfloat162float(H.b[0]));
    H.b[1] = __float2bfloat16(v.y); L.b[1] = __float2bfloat16(v.y - __bfloat162float(H.b[1]));
    H.b[2] = __float2bfloat16(v.z); L.b[2] = __float2bfloat16(v.z - __bfloat162float(H.b[2]));
    H.b[3] = __float2bfloat16(v.w); L.b[3] = __float2bfloat16(v.w - __bfloat162float(H.b[3]));
    ((uint2*)g_xhi)[i] = H.u;
    ((uint2*)g_xlo)[i] = L.u;
}

__global__ void zero_pad_kernel(int M) {
    int i = blockIdx.x * blockDim.x + threadIdx.x;
    size_t base = (size_t)M * CH;
    size_t total = (size_t)PAD_M * CH;
    size_t idx = base + i;
    if (idx < total) {
        g_xhi[idx] = __float2bfloat16(0.f);
        g_xlo[idx] = __float2bfloat16(0.f);
    }
}

__global__ void split_wt_kernel(const float* __restrict__ W) {
    int k = threadIdx.x;
    int n = blockIdx.x;
    float w = W[k * CH + n];
    __nv_bfloat16 h = __float2bfloat16(w);
    g_wthi[n * CH + k] = h;
    g_wtlo[n * CH + k] = __float2bfloat16(w - __bfloat162float(h));
}

// =============================================================== mma.sync GEMM
// g_xw[M, bn..bn+127] = x @ W[:, bn..bn+127] via split-bf16
// (D += AhiBhi + AhiBlo + AloBhi, fp32 accum). One N-half per launch for
// channel-pipelined overlap with the gather.
#define SWZ(r, c) ((uint32_t)((r) * 64 + (((c) ^ ((r) & 3)) * 16)))
#define GEMM_SMEM 65536

__global__ __launch_bounds__(256, 2) void gemm_mma(int M, int bn) {
    extern __shared__ char smem[];
    const uint32_t sb = smem_u32(smem);
    const int tid  = threadIdx.x;
    const int lane = tid & 31;
    const int wid  = tid >> 5;
    const int warp_m = (wid & 3) * 32;   // 0,32,64,96
    const int warp_n = (wid >> 2) * 64;  // 0,64
    const size_t arow = (size_t)blockIdx.x * 128;

    float acc[2][8][4];
    #pragma unroll
    for (int mt = 0; mt < 2; mt++)
        #pragma unroll
        for (int nt = 0; nt < 8; nt++)
            #pragma unroll
            for (int j = 0; j < 4; j++) acc[mt][nt][j] = 0.f;

    auto fill = [&](int buf, int ch) {
        const int k0 = ch * 32;
        const uint32_t base = sb + buf * 32768;
        #pragma unroll
        for (int i = 0; i < 2; i++) {
            int chunk = tid + i * 256;         // 0..511
            int r = chunk >> 2, c = chunk & 3; // row 0..127, 16B-chunk 0..3
            uint32_t so = SWZ(r, c);
            size_t ga = (arow + r) * CH + k0 + c * 8;
            size_t gb = (size_t)(bn + r) * CH + k0 + c * 8;
            cp_async16(base +     0 + so, &g_xhi[ga]);
            cp_async16(base +  8192 + so, &g_xlo[ga]);
            cp_async16(base + 16384 + so, &g_wthi[gb]);
            cp_async16(base + 24576 + so, &g_wtlo[gb]);
        }
    };

    auto compute = [&](int buf) {
        const uint32_t base = sb + buf * 32768;
        #pragma unroll
        for (int ks = 0; ks < 2; ks++) {
            uint32_t a_hi[2][4], a_lo[2][4];
            const int achunk = 2 * ks + (lane >> 4);
            #pragma unroll
            for (int mt = 0; mt < 2; mt++) {
                int r = warp_m + mt * 16 + (lane & 15);
                uint32_t ad = base + SWZ(r, achunk);
                ldsm_x4(a_hi[mt], ad);
                ldsm_x4(a_lo[mt], ad + 8192);
            }
            #pragma unroll
            for (int np = 0; np < 4; np++) {
                int nr = warp_n + np * 16 + (lane & 7) + ((lane & 16) ? 8 : 0);
                int bchunk = 2 * ks + ((lane >> 3) & 1);
                uint32_t bd = base + 16384 + SWZ(nr, bchunk);
                uint32_t bhi[4], blo[4];
                ldsm_x4(bhi, bd);
                ldsm_x4(blo, bd + 8192);
                #pragma unroll
                for (int h = 0; h < 2; h++) {
                    int nt = np * 2 + h;
                    #pragma unroll
                    for (int mt = 0; mt < 2; mt++) {
                        mma_bf16(acc[mt][nt], a_hi[mt], &bhi[2 * h]);
                        mma_bf16(acc[mt][nt], a_hi[mt], &blo[2 * h]);
                        mma_bf16(acc[mt][nt], a_lo[mt], &bhi[2 * h]);
                    }
                }
            }
        }
    };

    fill(0, 0);
    cp_commit();
    #pragma unroll 1
    for (int ch = 0; ch < 8; ch++) {
        if (ch < 7) {
            fill((ch + 1) & 1, ch + 1);
            cp_commit();
            cp_wait<1>();
        } else {
            cp_wait<0>();
        }
        __syncthreads();
        compute(ch & 1);
        __syncthreads();
    }

    #pragma unroll
    for (int mt = 0; mt < 2; mt++) {
        size_t r0 = arow + warp_m + mt * 16 + (lane >> 2);
        #pragma unroll
        for (int nt = 0; nt < 8; nt++) {
            int gc = bn + warp_n + nt * 8 + 2 * (lane & 3);
            if (r0 < (size_t)M)
                *(float2*)&g_xw[r0 * CH + gc] =
                    make_float2(acc[mt][nt][0], acc[mt][nt][1]);
            if (r0 + 8 < (size_t)M)
                *(float2*)&g_xw[(r0 + 8) * CH + gc] =
                    make_float2(acc[mt][nt][2], acc[mt][nt][3]);
        }
    }
}

// =============================================================== gather
// out[d][c0+c] = b[c0+c] + sum_{edges to d} val * xw[src][c0+c]
// One 128-channel half per launch; 8 nodes per 256-thread block,
// 32 threads x float4 per node.
__global__ __launch_bounds__(256) void gather_half(const float* __restrict__ bias,
                                                   float* __restrict__ out, int c0) {
    int node = blockIdx.x * 8 + (threadIdx.x >> 5);
    if (node >= NN) return;
    int c = c0 + ((threadIdx.x & 31) << 2);
    int s = g_off[node], e = g_off[node + 1];
    float4 acc = *(const float4*)&bias[c];
    int j = s;
    for (; j + 4 <= e; j += 4) {
        int   s0 = g_esrc[j],     s1 = g_esrc[j + 1];
        int   s2 = g_esrc[j + 2], s3 = g_esrc[j + 3];
        float v0 = g_eval[j],     v1 = g_eval[j + 1];
        float v2 = g_eval[j + 2], v3 = g_eval[j + 3];
        float4 x0 = *(const float4*)&g_xw[(size_t)s0 * CH + c];
        float4 x1 = *(const float4*)&g_xw[(size_t)s1 * CH + c];
        float4 x2 = *(const float4*)&g_xw[(size_t)s2 * CH + c];
        float4 x3 = *(const float4*)&g_xw[(size_t)s3 * CH + c];
        acc.x += v0 * x0.x; acc.y += v0 * x0.y; acc.z += v0 * x0.z; acc.w += v0 * x0.w;
        acc.x += v1 * x1.x; acc.y += v1 * x1.y; acc.z += v1 * x1.z; acc.w += v1 * x1.w;
        acc.x += v2 * x2.x; acc.y += v2 * x2.y; acc.z += v2 * x2.z; acc.w += v2 * x2.w;
        acc.x += v3 * x3.x; acc.y += v3 * x3.y; acc.z += v3 * x3.z; acc.w += v3 * x3.w;
    }
    for (; j < e; ++j) {
        float v = g_eval[j];
        float4 x0 = *(const float4*)&g_xw[(size_t)g_esrc[j] * CH + c];
        acc.x += v * x0.x; acc.y += v * x0.y; acc.z += v * x0.z; acc.w += v * x0.w;
    }
    *(float4*)&out[(size_t)node * CH + c] = acc;
}

// =============================================================== launch
// DAG (captured with forked streams so branches overlap at replay):
//   main:  split_x -> pad -> split_wt -> gemm(n=0..127) -> gemm(n=128..255)
//   sB:    memset(deg) -> hist -> scan -> scatter
//   sC:    [gemm0 && scatter] -> gather cols 0..127
//   main:  [gemm1 && scatter] -> gather cols 128..255 -> join sC
extern "C" void kernel_launch(void* const* d_in, const int* in_sizes, int n_in,
                              void* d_out, int out_size) {
    const float* x    = (const float*)d_in[0];   // [N, 256]
    const float* W    = (const float*)d_in[1];   // [256, 256]
    const float* bias = (const float*)d_in[2];   // [256]
    const int*   esrc = (const int*)d_in[3];     // [E]
    const int*   edst = (const int*)d_in[4];     // [E]
    const float* eval = (const float*)d_in[5];   // [E]
    float* out = (float*)d_out;

    int M = in_sizes[0] / CH;   // 50000
    int E = in_sizes[3];        // 800000

    cudaFuncSetAttribute(gemm_mma, cudaFuncAttributeMaxDynamicSharedMemorySize,
                         GEMM_SMEM);

    cudaStream_t sB, sC;
    cudaStreamCreateWithFlags(&sB, cudaStreamNonBlocking);
    cudaStreamCreateWithFlags(&sC, cudaStreamNonBlocking);
    cudaEvent_t evRoot, evS, evG0, evC;
    cudaEventCreateWithFlags(&evRoot, cudaEventDisableTiming);
    cudaEventCreateWithFlags(&evS,    cudaEventDisableTiming);
    cudaEventCreateWithFlags(&evG0,   cudaEventDisableTiming);
    cudaEventCreateWithFlags(&evC,    cudaEventDisableTiming);

    // fork sB off the (captured) default stream
    cudaEventRecord(evRoot, 0);
    cudaStreamWaitEvent(sB, evRoot, 0);

    // ---- branch B: CSR-by-dst build ----
    void* degp = nullptr;
    cudaGetSymbolAddress(&degp, g_deg);
    cudaMemsetAsync(degp, 0, NN * sizeof(int), sB);
    hist_kernel<<<(E + 255) / 256, 256, 0, sB>>>(edst, E);
    scan_kernel<<<1, 1024, 0, sB>>>(E);
    scatter_kernel<<<(E + 255) / 256, 256, 0, sB>>>(esrc, edst, eval, E);
    cudaEventRecord(evS, sB);

    // ---- main branch: split prep + GEMM halves ----
    int n4 = (M * CH) / 4;
    split_x_kernel<<<(n4 + 255) / 256, 256>>>(x, n4);
    int padn = (PAD_M - M) * CH;
    if (padn > 0) zero_pad_kernel<<<(padn + 255) / 256, 256>>>(M);
    split_wt_kernel<<<CH, CH>>>(W);
    int mblk = (M + 127) / 128;   // 391
    gemm_mma<<<mblk, 256, GEMM_SMEM>>>(M, 0);
    cudaEventRecord(evG0, 0);
    gemm_mma<<<mblk, 256, GEMM_SMEM>>>(M, 128);

    // ---- branch C: gather cols 0..127 (overlaps gemm half 1) ----
    cudaStreamWaitEvent(sC, evG0, 0);
    cudaStreamWaitEvent(sC, evS, 0);
    gather_half<<<(NN + 7) / 8, 256, 0, sC>>>(bias, out, 0);
    cudaEventRecord(evC, sC);

    // ---- main branch: gather cols 128..255, then join everything ----
    cudaStreamWaitEvent(0, evS, 0);
    gather_half<<<(NN + 7) / 8, 256>>>(bias, out, 128);
    cudaStreamWaitEvent(0, evC, 0);

    cudaEventDestroy(evRoot);
    cudaEventDestroy(evS);
    cudaEventDestroy(evG0);
    cudaEventDestroy(evC);
    cudaStreamDestroy(sB);
    cudaStreamDestroy(sC);
}